// round 2
// baseline (speedup 1.0000x reference)
#include <cuda_runtime.h>
#include <cstdint>
#include <cstddef>

#define N_STATE  1280
#define N_HEAD   20
#define HEAD_DIM 64
#define N_CTX    32
#define CACHE    16384
#define CHUNK    256
#define NCHUNK   (CACHE / CHUNK)   // 64

// ---------------- scratch (device globals; no allocation allowed) ----------
__device__ float g_q[N_CTX * N_STATE];       // scaled q projection
__device__ float g_k[N_CTX * N_STATE];       // new k rows
__device__ float g_v[N_CTX * N_STATE];       // new v rows
__device__ float g_oattn[N_CTX * N_STATE];   // attention output (pre out-proj)
__device__ int   g_posmap[CACHE];            // cache row -> new-row index or -1
__device__ float g_m[N_HEAD * NCHUNK * N_CTX];
__device__ float g_l[N_HEAD * NCHUNK * N_CTX];
__device__ float g_opart[(size_t)N_HEAD * NCHUNK * N_CTX * HEAD_DIM];

// ---------------- packed fp32x2 helpers (sm_103a FFMA2 path) ---------------
__device__ __forceinline__ void fmaf2(unsigned long long& d,
                                      unsigned long long a,
                                      unsigned long long b) {
    asm("fma.rn.f32x2 %0, %1, %2, %0;" : "+l"(d) : "l"(a), "l"(b));
}
__device__ __forceinline__ unsigned long long pack2(float lo, float hi) {
    unsigned long long r;
    asm("mov.b64 %0, {%1, %2};"
        : "=l"(r) : "r"(__float_as_uint(lo)), "r"(__float_as_uint(hi)));
    return r;
}
__device__ __forceinline__ float2 unpack2(unsigned long long v) {
    unsigned int lo, hi;
    asm("mov.b64 {%0, %1}, %2;" : "=r"(lo), "=r"(hi) : "l"(v));
    return make_float2(__uint_as_float(lo), __uint_as_float(hi));
}

// ---------------- position map -------------------------------------------
__global__ __launch_bounds__(256) void k_map_init() {
    int t = blockIdx.x * 256 + threadIdx.x;
    if (t < CACHE) g_posmap[t] = -1;
}
__global__ __launch_bounds__(32) void k_map_scatter(const int* __restrict__ pos, int n) {
    int i = threadIdx.x;
    if (i < n) {
        int p = pos[i];
        if (p >= 0 && p < CACHE) g_posmap[p] = i;
    }
}

// ---------------- tiled 32-row GEMM: Y[32,1280] = X @ W^T (+bias)*scale ----
// 256 threads, 32 output cols per block. ws/xs rows padded to 68 floats
// (17 16B-units, coprime with 32 -> conflict-free LDS.128).
__device__ __forceinline__ void gemm_32rows(const float* __restrict__ X,
                                            const float* __restrict__ W,
                                            const float* __restrict__ bias,
                                            float scale,
                                            float* __restrict__ Y,
                                            int c0) {
    __shared__ float ws[32 * 68];
    __shared__ float xs[32 * 68];
    int tid = threadIdx.x;
    int cL  = tid & 31;        // output column within block
    int rG  = tid >> 5;        // 0..7, each handles 4 rows
    unsigned long long acc[4] = {0ull, 0ull, 0ull, 0ull};

    for (int kt = 0; kt < N_STATE; kt += 64) {
#pragma unroll
        for (int it = 0; it < 2; ++it) {
            int f = tid + it * 256;            // 0..511 over 32x16 float4s
            int row = f >> 4, k4 = f & 15;
            *(float4*)(ws + row * 68 + k4 * 4) =
                *(const float4*)(W + (size_t)(c0 + row) * N_STATE + kt + k4 * 4);
            *(float4*)(xs + row * 68 + k4 * 4) =
                *(const float4*)(X + (size_t)row * N_STATE + kt + k4 * 4);
        }
        __syncthreads();
#pragma unroll
        for (int k4 = 0; k4 < 16; ++k4) {
            ulonglong2 wv = *(const ulonglong2*)(ws + cL * 68 + k4 * 4);
#pragma unroll
            for (int j = 0; j < 4; ++j) {
                ulonglong2 xv = *(const ulonglong2*)(xs + (rG * 4 + j) * 68 + k4 * 4);
                fmaf2(acc[j], wv.x, xv.x);
                fmaf2(acc[j], wv.y, xv.y);
            }
        }
        __syncthreads();
    }
    int c = c0 + cL;
    float b = bias ? bias[c] : 0.0f;
#pragma unroll
    for (int j = 0; j < 4; ++j) {
        float2 s = unpack2(acc[j]);
        Y[(size_t)(rG * 4 + j) * N_STATE + c] = (s.x + s.y + b) * scale;
    }
}

__global__ __launch_bounds__(256) void k_qkv_gemm(const float* __restrict__ x,
                                                  const float* __restrict__ Wq,
                                                  const float* __restrict__ bq,
                                                  const float* __restrict__ Wk,
                                                  const float* __restrict__ Wv,
                                                  const float* __restrict__ bv) {
    int m = blockIdx.y;
    const float* W    = (m == 0) ? Wq : ((m == 1) ? Wk : Wv);
    const float* bias = (m == 0) ? bq : ((m == 1) ? (const float*)nullptr : bv);
    float scale       = (m == 0) ? 0.125f : 1.0f;   // fold HEAD_DIM^-0.5 into q
    float* Y          = (m == 0) ? g_q : ((m == 1) ? g_k : g_v);
    gemm_32rows(x, W, bias, scale, Y, blockIdx.x * 32);
}

__global__ __launch_bounds__(256) void k_out_gemm(const float* __restrict__ W,
                                                   const float* __restrict__ b,
                                                   float* __restrict__ Y) {
    gemm_32rows(g_oattn, W, b, 1.0f, Y, blockIdx.x * 32);
}

// ---------------- fused cache-copy + split-T attention ---------------------
// grid (20 heads, 64 chunks), 256 threads. Dynamic smem layout:
//   qs[32*64], S[256*33] (padded), kv[256*68] (padded, reused for k then v)
#define ATTN_SMEM_FLOATS (2048 + 256 * 33 + 256 * 68)
#define ATTN_SMEM_BYTES  (ATTN_SMEM_FLOATS * 4)

__global__ __launch_bounds__(256, 1) void k_attn(const float* __restrict__ kin,
                                                 const float* __restrict__ vin,
                                                 const float* __restrict__ mask,
                                                 float* __restrict__ kc,
                                                 float* __restrict__ vc) {
    extern __shared__ float smem_f[];
    float* qs = smem_f;                    // 2048
    float* S  = smem_f + 2048;             // 256*33
    float* kv = smem_f + 2048 + 256 * 33;  // 256*68

    int h   = blockIdx.x;
    int c   = blockIdx.y;
    int t0  = c * CHUNK;
    int tid = threadIdx.x;

    // load q tile (already scaled by 0.125)
#pragma unroll
    for (int it = 0; it < 8; ++it) {
        int i = tid + it * 256;   // 0..2047
        qs[i] = g_q[(size_t)(i >> 6) * N_STATE + h * HEAD_DIM + (i & 63)];
    }

    // cooperative K load: gmem (or new-k) -> smem, and write the kc copy
#pragma unroll
    for (int it = 0; it < 16; ++it) {
        int f = tid + it * 256;
        int row = f >> 4, d4 = f & 15;
        int tt = t0 + row;
        int mi = g_posmap[tt];
        const float* src = (mi >= 0) ? (g_k + (size_t)mi * N_STATE + h * HEAD_DIM)
                                     : (kin + (size_t)tt * N_STATE + h * HEAD_DIM);
        float4 vv = *(const float4*)(src + d4 * 4);
        *(float4*)(kc + (size_t)tt * N_STATE + h * HEAD_DIM + d4 * 4) = vv;
        *(float4*)(kv + row * 68 + d4 * 4) = vv;
    }
    __syncthreads();

    // QK^T: thread = one token; two passes of 16 query accumulators
    // (caps live u64 accs at 32 regs; kv row is re-read from SMEM, cheap)
#pragma unroll
    for (int half = 0; half < 2; ++half) {
        unsigned long long acc[16];
#pragma unroll
        for (int q = 0; q < 16; ++q) acc[q] = 0ull;
#pragma unroll
        for (int d4 = 0; d4 < 16; ++d4) {
            ulonglong2 kx = *(const ulonglong2*)(kv + tid * 68 + d4 * 4);
#pragma unroll
            for (int q = 0; q < 16; ++q) {
                ulonglong2 qv = *(const ulonglong2*)(qs + (half * 16 + q) * 64 + d4 * 4);
                fmaf2(acc[q], kx.x, qv.x);
                fmaf2(acc[q], kx.y, qv.y);
            }
        }
#pragma unroll
        for (int q = 0; q < 16; ++q) {
            int qq = half * 16 + q;
            float2 s = unpack2(acc[q]);
            S[tid * 33 + qq] = s.x + s.y + mask[(size_t)qq * CACHE + t0 + tid];
        }
    }
    __syncthreads();

    // chunk-local softmax stats: warp w owns queries 4w..4w+3
    {
        int w = tid >> 5, lane = tid & 31;
        for (int qq = 0; qq < 4; ++qq) {
            int q = w * 4 + qq;
            float vals[8];
            float mx = -1e30f;
#pragma unroll
            for (int i = 0; i < 8; ++i) {
                vals[i] = S[(lane + 32 * i) * 33 + q];
                mx = fmaxf(mx, vals[i]);
            }
#pragma unroll
            for (int off = 16; off > 0; off >>= 1)
                mx = fmaxf(mx, __shfl_xor_sync(0xffffffffu, mx, off));
            float sum = 0.f;
#pragma unroll
            for (int i = 0; i < 8; ++i) {
                float p = __expf(vals[i] - mx);
                S[(lane + 32 * i) * 33 + q] = p;
                sum += p;
            }
#pragma unroll
            for (int off = 16; off > 0; off >>= 1)
                sum += __shfl_xor_sync(0xffffffffu, sum, off);
            if (lane == 0) {
                int pi = (h * NCHUNK + c) * N_CTX + q;
                g_m[pi] = mx;
                g_l[pi] = sum;
            }
        }
    }
    __syncthreads();

    // cooperative V load (overwrite kv) + vc copy
#pragma unroll
    for (int it = 0; it < 16; ++it) {
        int f = tid + it * 256;
        int row = f >> 4, d4 = f & 15;
        int tt = t0 + row;
        int mi = g_posmap[tt];
        const float* src = (mi >= 0) ? (g_v + (size_t)mi * N_STATE + h * HEAD_DIM)
                                     : (vin + (size_t)tt * N_STATE + h * HEAD_DIM);
        float4 vv = *(const float4*)(src + d4 * 4);
        *(float4*)(vc + (size_t)tt * N_STATE + h * HEAD_DIM + d4 * 4) = vv;
        *(float4*)(kv + row * 68 + d4 * 4) = vv;
    }
    __syncthreads();

    // PV: thread = (query q, 8-wide d group), packed f32x2 accumulation
    {
        int q = tid >> 3, dg = tid & 7;
        unsigned long long o[4] = {0ull, 0ull, 0ull, 0ull};
        for (int t = 0; t < CHUNK; ++t) {
            float p = S[t * 33 + q];
            unsigned long long p2 = pack2(p, p);
            ulonglong2 va = *(const ulonglong2*)(kv + t * 68 + dg * 8);
            fmaf2(o[0], p2, va.x);
            fmaf2(o[1], p2, va.y);
            ulonglong2 vb = *(const ulonglong2*)(kv + t * 68 + dg * 8 + 4);
            fmaf2(o[2], p2, vb.x);
            fmaf2(o[3], p2, vb.y);
        }
        int pi = (h * NCHUNK + c) * N_CTX + q;
        float* dst = g_opart + (size_t)pi * HEAD_DIM + dg * 8;
#pragma unroll
        for (int j = 0; j < 4; ++j) {
            float2 s = unpack2(o[j]);
            dst[j * 2 + 0] = s.x;
            dst[j * 2 + 1] = s.y;
        }
    }
}

// ---------------- split-T reduction: combine 64 chunk partials -------------
__global__ __launch_bounds__(64) void k_reduce() {
    int h = blockIdx.x >> 5;   // 20 heads * 32 queries
    int q = blockIdx.x & 31;
    int d = threadIdx.x;
    __shared__ float smx[NCHUNK], sl[NCHUNK];
    smx[d] = g_m[(h * NCHUNK + d) * N_CTX + q];
    sl[d]  = g_l[(h * NCHUNK + d) * N_CTX + q];
    __syncthreads();
    float M = -1e30f;
#pragma unroll
    for (int cc = 0; cc < NCHUNK; ++cc) M = fmaxf(M, smx[cc]);
    float L = 0.f, o = 0.f;
    for (int cc = 0; cc < NCHUNK; ++cc) {
        float wc = __expf(smx[cc] - M);
        L += wc * sl[cc];
        o += wc * g_opart[((size_t)(h * NCHUNK + cc) * N_CTX + q) * HEAD_DIM + d];
    }
    g_oattn[(size_t)q * N_STATE + h * HEAD_DIM + d] = o / L;
}

// ---------------- launch ---------------------------------------------------
extern "C" void kernel_launch(void* const* d_in, const int* in_sizes, int n_in,
                              void* d_out, int out_size) {
    (void)n_in; (void)out_size;
    const float* x    = (const float*)d_in[0];
    const float* kin  = (const float*)d_in[1];
    const float* vin  = (const float*)d_in[2];
    const int*   pos  = (const int*)d_in[3];
    const float* mask = (const float*)d_in[4];
    const float* Wq   = (const float*)d_in[5];
    const float* bq   = (const float*)d_in[6];
    const float* Wk   = (const float*)d_in[7];
    const float* Wv   = (const float*)d_in[8];
    const float* bv   = (const float*)d_in[9];
    const float* Wout = (const float*)d_in[10];
    const float* bout = (const float*)d_in[11];

    float* out = (float*)d_out;                       // [32,1280]
    float* kc  = out + (size_t)N_CTX * N_STATE;       // [16384,1280]
    float* vc  = kc + (size_t)CACHE * N_STATE;        // [16384,1280]

    (void)cudaFuncSetAttribute(k_attn, cudaFuncAttributeMaxDynamicSharedMemorySize,
                               ATTN_SMEM_BYTES);

    k_map_init<<<CACHE / 256, 256>>>();
    k_map_scatter<<<1, 32>>>(pos, in_sizes[3]);
    k_qkv_gemm<<<dim3(N_STATE / 32, 3), 256>>>(x, Wq, bq, Wk, Wv, bv);
    k_attn<<<dim3(N_HEAD, NCHUNK), 256, ATTN_SMEM_BYTES>>>(kin, vin, mask, kc, vc);
    k_reduce<<<N_HEAD * N_CTX, 64>>>();
    k_out_gemm<<<N_STATE / 32, 256>>>(Wout, bout, out);
}

// round 3
// speedup vs baseline: 1.5386x; 1.5386x over previous
#include <cuda_runtime.h>
#include <cstdint>
#include <cstddef>

#define N_STATE  1280
#define N_HEAD   20
#define HEAD_DIM 64
#define N_CTX    32
#define CACHE    16384
#define CHUNK    128
#define NCHUNK   (CACHE / CHUNK)   // 128

// ---------------- scratch (device globals; no allocation allowed) ----------
__device__ float g_q[N_CTX * N_STATE];       // scaled q projection
__device__ float g_k[N_CTX * N_STATE];       // new k rows
__device__ float g_v[N_CTX * N_STATE];       // new v rows
__device__ float g_oattn[N_CTX * N_STATE];   // attention output (pre out-proj)
__device__ int   g_posmap[CACHE];            // cache row -> new-row index or -1
__device__ float g_m[N_HEAD * NCHUNK * N_CTX];
__device__ float g_l[N_HEAD * NCHUNK * N_CTX];
__device__ float g_opart[(size_t)N_HEAD * NCHUNK * N_CTX * HEAD_DIM];

// ---------------- packed fp32x2 helpers (sm_103a FFMA2 path) ---------------
__device__ __forceinline__ void fmaf2(unsigned long long& d,
                                      unsigned long long a,
                                      unsigned long long b) {
    asm("fma.rn.f32x2 %0, %1, %2, %0;" : "+l"(d) : "l"(a), "l"(b));
}
__device__ __forceinline__ unsigned long long pack2(float lo, float hi) {
    unsigned long long r;
    asm("mov.b64 %0, {%1, %2};"
        : "=l"(r) : "r"(__float_as_uint(lo)), "r"(__float_as_uint(hi)));
    return r;
}
__device__ __forceinline__ float2 unpack2(unsigned long long v) {
    unsigned int lo, hi;
    asm("mov.b64 {%0, %1}, %2;" : "=r"(lo), "=r"(hi) : "l"(v));
    return make_float2(__uint_as_float(lo), __uint_as_float(hi));
}

// ---------------- cp.async helpers -----------------------------------------
__device__ __forceinline__ unsigned smem_u32(const void* p) {
    return (unsigned)__cvta_generic_to_shared(p);
}
__device__ __forceinline__ void cp16(unsigned dst, const void* src) {
    asm volatile("cp.async.ca.shared.global [%0], [%1], 16;" :: "r"(dst), "l"(src));
}
__device__ __forceinline__ void cp4(unsigned dst, const void* src) {
    asm volatile("cp.async.ca.shared.global [%0], [%1], 4;" :: "r"(dst), "l"(src));
}
#define CP_COMMIT()  asm volatile("cp.async.commit_group;")
#define CP_WAIT(n)   asm volatile("cp.async.wait_group %0;" :: "n"(n))

// ---------------- position map ---------------------------------------------
__global__ __launch_bounds__(256) void k_map_init() {
    int t = blockIdx.x * 256 + threadIdx.x;
    if (t < CACHE) g_posmap[t] = -1;
}
__global__ __launch_bounds__(32) void k_map_scatter(const int* __restrict__ pos, int n) {
    int i = threadIdx.x;
    if (i < n) {
        int p = pos[i];
        if (p >= 0 && p < CACHE) g_posmap[p] = i;
    }
}

// ---------------- tiled 32-row GEMM: Y[32,1280] = X @ W^T (+bias)*scale ----
__device__ __forceinline__ void gemm_32rows(const float* __restrict__ X,
                                            const float* __restrict__ W,
                                            const float* __restrict__ bias,
                                            float scale,
                                            float* __restrict__ Y,
                                            int c0) {
    __shared__ float ws[32 * 68];
    __shared__ float xs[32 * 68];
    int tid = threadIdx.x;
    int cL  = tid & 31;
    int rG  = tid >> 5;
    unsigned long long acc[4] = {0ull, 0ull, 0ull, 0ull};

    for (int kt = 0; kt < N_STATE; kt += 64) {
#pragma unroll
        for (int it = 0; it < 2; ++it) {
            int f = tid + it * 256;
            int row = f >> 4, k4 = f & 15;
            cp16(smem_u32(ws + row * 68 + k4 * 4),
                 W + (size_t)(c0 + row) * N_STATE + kt + k4 * 4);
            cp16(smem_u32(xs + row * 68 + k4 * 4),
                 X + (size_t)row * N_STATE + kt + k4 * 4);
        }
        CP_COMMIT();
        CP_WAIT(0);
        __syncthreads();
#pragma unroll
        for (int k4 = 0; k4 < 16; ++k4) {
            ulonglong2 wv = *(const ulonglong2*)(ws + cL * 68 + k4 * 4);
#pragma unroll
            for (int j = 0; j < 4; ++j) {
                ulonglong2 xv = *(const ulonglong2*)(xs + (rG * 4 + j) * 68 + k4 * 4);
                fmaf2(acc[j], wv.x, xv.x);
                fmaf2(acc[j], wv.y, xv.y);
            }
        }
        __syncthreads();
    }
    int c = c0 + cL;
    float b = bias ? bias[c] : 0.0f;
#pragma unroll
    for (int j = 0; j < 4; ++j) {
        float2 s = unpack2(acc[j]);
        Y[(size_t)(rG * 4 + j) * N_STATE + c] = (s.x + s.y + b) * scale;
    }
}

__global__ __launch_bounds__(256) void k_qkv_gemm(const float* __restrict__ x,
                                                  const float* __restrict__ Wq,
                                                  const float* __restrict__ bq,
                                                  const float* __restrict__ Wk,
                                                  const float* __restrict__ Wv,
                                                  const float* __restrict__ bv) {
    int m = blockIdx.y;
    const float* W    = (m == 0) ? Wq : ((m == 1) ? Wk : Wv);
    const float* bias = (m == 0) ? bq : ((m == 1) ? (const float*)nullptr : bv);
    float scale       = (m == 0) ? 0.125f : 1.0f;
    float* Y          = (m == 0) ? g_q : ((m == 1) ? g_k : g_v);
    gemm_32rows(x, W, bias, scale, Y, blockIdx.x * 32);
}

__global__ __launch_bounds__(256) void k_out_gemm(const float* __restrict__ W,
                                                   const float* __restrict__ b,
                                                   float* __restrict__ Y) {
    gemm_32rows(g_oattn, W, b, 1.0f, Y, blockIdx.x * 32);
}

// ---------------- fused cache-copy + split-T attention ---------------------
// grid (20 heads, 128 chunks of 128 tokens), 256 threads, 2 CTAs/SM.
// smem: qs[32*64] | S[128*33] (mask staged, then scores) | kK[128*68] | kV[128*68]
#define SM_QS  0
#define SM_S   2048
#define SM_KK  (2048 + 128 * 33)
#define SM_KV  (SM_KK + 128 * 68)
#define ATTN_SMEM_FLOATS (SM_KV + 128 * 68)
#define ATTN_SMEM_BYTES  (ATTN_SMEM_FLOATS * 4)

__global__ __launch_bounds__(256, 2) void k_attn(const float* __restrict__ kin,
                                                 const float* __restrict__ vin,
                                                 const float* __restrict__ mask,
                                                 float* __restrict__ kc,
                                                 float* __restrict__ vc) {
    extern __shared__ float sm[];
    float* qs = sm + SM_QS;
    float* S  = sm + SM_S;
    float* kK = sm + SM_KK;
    float* kV = sm + SM_KV;

    int h   = blockIdx.x;
    int c   = blockIdx.y;
    int t0  = c * CHUNK;
    int tid = threadIdx.x;

    // ---- group 1: q tile (16B) + mask tile (4B, staged into S slots) ----
#pragma unroll
    for (int it = 0; it < 2; ++it) {
        int i = tid + it * 256;               // 0..511 float4s of q
        int row = i >> 4, d4 = i & 15;
        cp16(smem_u32(qs + row * 64 + d4 * 4),
             g_q + (size_t)row * N_STATE + h * HEAD_DIM + d4 * 4);
    }
#pragma unroll
    for (int it = 0; it < 16; ++it) {
        int f = tid + it * 256;               // 0..4095
        int q = f >> 7, t = f & 127;          // consecutive lanes -> consecutive t
        cp4(smem_u32(S + t * 33 + q), mask + (size_t)q * CACHE + t0 + t);
    }
    CP_COMMIT();

    // ---- group 2: K tile (posmap-substituted) ----
#pragma unroll
    for (int it = 0; it < 8; ++it) {
        int f = tid + it * 256;               // 0..2047
        int row = f >> 4, d4 = f & 15;
        int tt = t0 + row;
        int mi = g_posmap[tt];
        const float* src = (mi >= 0) ? (g_k + (size_t)mi * N_STATE + h * HEAD_DIM)
                                     : (kin + (size_t)tt * N_STATE + h * HEAD_DIM);
        cp16(smem_u32(kK + row * 68 + d4 * 4), src + d4 * 4);
    }
    CP_COMMIT();

    // ---- group 3: V tile ----
#pragma unroll
    for (int it = 0; it < 8; ++it) {
        int f = tid + it * 256;
        int row = f >> 4, d4 = f & 15;
        int tt = t0 + row;
        int mi = g_posmap[tt];
        const float* src = (mi >= 0) ? (g_v + (size_t)mi * N_STATE + h * HEAD_DIM)
                                     : (vin + (size_t)tt * N_STATE + h * HEAD_DIM);
        cp16(smem_u32(kV + row * 68 + d4 * 4), src + d4 * 4);
    }
    CP_COMMIT();

    CP_WAIT(1);            // q + mask + K complete (V still in flight)
    __syncthreads();

    // kc copy from smem (fire-and-forget stores, overlap with QK)
#pragma unroll
    for (int it = 0; it < 8; ++it) {
        int f = tid + it * 256;
        int row = f >> 4, d4 = f & 15;
        int tt = t0 + row;
        float4 vv = *(const float4*)(kK + row * 68 + d4 * 4);
        *(float4*)(kc + (size_t)tt * N_STATE + h * HEAD_DIM + d4 * 4) = vv;
    }

    // ---- QK^T: thread = (token, query-half); 16 packed accumulators ----
    {
        int tok = tid & 127;
        int qh  = tid >> 7;                   // 0 or 1
        unsigned long long acc[16];
#pragma unroll
        for (int q = 0; q < 16; ++q) acc[q] = 0ull;
#pragma unroll
        for (int d4 = 0; d4 < 16; ++d4) {
            ulonglong2 kx = *(const ulonglong2*)(kK + tok * 68 + d4 * 4);
#pragma unroll
            for (int q = 0; q < 16; ++q) {
                ulonglong2 qv = *(const ulonglong2*)(qs + (qh * 16 + q) * 64 + d4 * 4);
                fmaf2(acc[q], kx.x, qv.x);
                fmaf2(acc[q], kx.y, qv.y);
            }
        }
#pragma unroll
        for (int q = 0; q < 16; ++q) {
            int qq = qh * 16 + q;
            float mval = S[tok * 33 + qq];    // staged mask (this thread owns slot)
            float2 s = unpack2(acc[q]);
            S[tok * 33 + qq] = s.x + s.y + mval;
        }
    }
    __syncthreads();

    // ---- chunk-local softmax stats: warp w owns queries 4w..4w+3 ----
    {
        int w = tid >> 5, lane = tid & 31;
#pragma unroll
        for (int qq = 0; qq < 4; ++qq) {
            int q = w * 4 + qq;
            float vals[4];
            float mx = -1e30f;
#pragma unroll
            for (int i = 0; i < 4; ++i) {
                vals[i] = S[(lane + 32 * i) * 33 + q];
                mx = fmaxf(mx, vals[i]);
            }
#pragma unroll
            for (int off = 16; off > 0; off >>= 1)
                mx = fmaxf(mx, __shfl_xor_sync(0xffffffffu, mx, off));
            float sum = 0.f;
#pragma unroll
            for (int i = 0; i < 4; ++i) {
                float p = __expf(vals[i] - mx);
                S[(lane + 32 * i) * 33 + q] = p;
                sum += p;
            }
#pragma unroll
            for (int off = 16; off > 0; off >>= 1)
                sum += __shfl_xor_sync(0xffffffffu, sum, off);
            if (lane == 0) {
                int pi = (h * NCHUNK + c) * N_CTX + q;
                g_m[pi] = mx;
                g_l[pi] = sum;
            }
        }
    }

    CP_WAIT(0);            // V tile complete
    __syncthreads();       // also publishes softmax S writes

    // vc copy from smem
#pragma unroll
    for (int it = 0; it < 8; ++it) {
        int f = tid + it * 256;
        int row = f >> 4, d4 = f & 15;
        int tt = t0 + row;
        float4 vv = *(const float4*)(kV + row * 68 + d4 * 4);
        *(float4*)(vc + (size_t)tt * N_STATE + h * HEAD_DIM + d4 * 4) = vv;
    }

    // ---- PV: thread = (query, 8-wide d group) ----
    {
        int q = tid >> 3, dg = tid & 7;
        unsigned long long o[4] = {0ull, 0ull, 0ull, 0ull};
#pragma unroll 4
        for (int t = 0; t < CHUNK; ++t) {
            float p = S[t * 33 + q];
            unsigned long long p2 = pack2(p, p);
            ulonglong2 va = *(const ulonglong2*)(kV + t * 68 + dg * 8);
            fmaf2(o[0], p2, va.x);
            fmaf2(o[1], p2, va.y);
            ulonglong2 vb = *(const ulonglong2*)(kV + t * 68 + dg * 8 + 4);
            fmaf2(o[2], p2, vb.x);
            fmaf2(o[3], p2, vb.y);
        }
        int pi = (h * NCHUNK + c) * N_CTX + q;
        float* dst = g_opart + (size_t)pi * HEAD_DIM + dg * 8;
#pragma unroll
        for (int j = 0; j < 4; ++j) {
            float2 s = unpack2(o[j]);
            dst[j * 2 + 0] = s.x;
            dst[j * 2 + 1] = s.y;
        }
    }
}

// ---------------- split-T reduction: combine 128 chunk partials ------------
__global__ __launch_bounds__(64) void k_reduce() {
    int h = blockIdx.x >> 5;   // 20 heads * 32 queries
    int q = blockIdx.x & 31;
    int d = threadIdx.x;
    __shared__ float smx[NCHUNK], sl[NCHUNK];
#pragma unroll
    for (int i = 0; i < NCHUNK / 64; ++i) {
        int cc = d + i * 64;
        smx[cc] = g_m[(h * NCHUNK + cc) * N_CTX + q];
        sl[cc]  = g_l[(h * NCHUNK + cc) * N_CTX + q];
    }
    __syncthreads();
    float M = -1e30f;
#pragma unroll
    for (int cc = 0; cc < NCHUNK; ++cc) M = fmaxf(M, smx[cc]);
    float L = 0.f, o = 0.f;
#pragma unroll 4
    for (int cc = 0; cc < NCHUNK; ++cc) {
        float wc = __expf(smx[cc] - M);
        L += wc * sl[cc];
        o += wc * g_opart[((size_t)(h * NCHUNK + cc) * N_CTX + q) * HEAD_DIM + d];
    }
    g_oattn[(size_t)q * N_STATE + h * HEAD_DIM + d] = o / L;
}

// ---------------- launch ---------------------------------------------------
extern "C" void kernel_launch(void* const* d_in, const int* in_sizes, int n_in,
                              void* d_out, int out_size) {
    (void)n_in; (void)out_size;
    const float* x    = (const float*)d_in[0];
    const float* kin  = (const float*)d_in[1];
    const float* vin  = (const float*)d_in[2];
    const int*   pos  = (const int*)d_in[3];
    const float* mask = (const float*)d_in[4];
    const float* Wq   = (const float*)d_in[5];
    const float* bq   = (const float*)d_in[6];
    const float* Wk   = (const float*)d_in[7];
    const float* Wv   = (const float*)d_in[8];
    const float* bv   = (const float*)d_in[9];
    const float* Wout = (const float*)d_in[10];
    const float* bout = (const float*)d_in[11];

    float* out = (float*)d_out;                       // [32,1280]
    float* kc  = out + (size_t)N_CTX * N_STATE;       // [16384,1280]
    float* vc  = kc + (size_t)CACHE * N_STATE;        // [16384,1280]

    (void)cudaFuncSetAttribute(k_attn, cudaFuncAttributeMaxDynamicSharedMemorySize,
                               ATTN_SMEM_BYTES);

    k_map_init<<<CACHE / 256, 256>>>();
    k_map_scatter<<<1, 32>>>(pos, in_sizes[3]);
    k_qkv_gemm<<<dim3(N_STATE / 32, 3), 256>>>(x, Wq, bq, Wk, Wv, bv);
    k_attn<<<dim3(N_HEAD, NCHUNK), 256, ATTN_SMEM_BYTES>>>(kin, vin, mask, kc, vc);
    k_reduce<<<N_HEAD * N_CTX, 64>>>();
    k_out_gemm<<<N_STATE / 32, 256>>>(Wout, bout, out);
}

// round 5
// speedup vs baseline: 3.1328x; 2.0362x over previous
#include <cuda_runtime.h>
#include <cstdint>
#include <cstddef>

#define N_STATE  1280
#define N_HEAD   20
#define HEAD_DIM 64
#define N_CTX    32
#define CACHE    16384
#define CHUNK    128
#define NCHUNK   (CACHE / CHUNK)   // 128

// strides (floats) chosen for bank-conflict-free mma fragment loads
#define KV_STR   76     // 12g+tg -> 32 distinct banks
#define S_STR    37     // 5*lane coprime 32 for softmax; <=2-way for PV A

// ---------------- scratch (device globals) ---------------------------------
__device__ float g_q[N_CTX * N_STATE];
__device__ float g_k[N_CTX * N_STATE];
__device__ float g_v[N_CTX * N_STATE];
__device__ float g_oattn[N_CTX * N_STATE];
__device__ int   g_posmap[CACHE];
__device__ float g_m[N_HEAD * NCHUNK * N_CTX];
__device__ float g_l[N_HEAD * NCHUNK * N_CTX];
__device__ float g_opart[(size_t)N_HEAD * NCHUNK * N_CTX * HEAD_DIM];

// ---------------- packed fp32x2 helpers ------------------------------------
__device__ __forceinline__ void fmaf2(unsigned long long& d,
                                      unsigned long long a,
                                      unsigned long long b) {
    asm("fma.rn.f32x2 %0, %1, %2, %0;" : "+l"(d) : "l"(a), "l"(b));
}
__device__ __forceinline__ float2 unpack2(unsigned long long v) {
    unsigned int lo, hi;
    asm("mov.b64 {%0, %1}, %2;" : "=r"(lo), "=r"(hi) : "l"(v));
    return make_float2(__uint_as_float(lo), __uint_as_float(hi));
}

// ---------------- mma tf32 helpers -----------------------------------------
__device__ __forceinline__ unsigned f2tf(float x) {
    unsigned r;
    asm("cvt.rna.tf32.f32 %0, %1;" : "=r"(r) : "f"(x));
    return r;
}
__device__ __forceinline__ void mma_tf32(float* d, const unsigned* a, const unsigned* b) {
    asm("mma.sync.aligned.m16n8k8.row.col.f32.tf32.tf32.f32 "
        "{%0,%1,%2,%3}, {%4,%5,%6,%7}, {%8,%9}, {%0,%1,%2,%3};"
        : "+f"(d[0]), "+f"(d[1]), "+f"(d[2]), "+f"(d[3])
        : "r"(a[0]), "r"(a[1]), "r"(a[2]), "r"(a[3]), "r"(b[0]), "r"(b[1]));
}

// ---------------- cp.async helpers -----------------------------------------
__device__ __forceinline__ unsigned smem_u32(const void* p) {
    return (unsigned)__cvta_generic_to_shared(p);
}
__device__ __forceinline__ void cp16(unsigned dst, const void* src) {
    asm volatile("cp.async.ca.shared.global [%0], [%1], 16;" :: "r"(dst), "l"(src));
}
__device__ __forceinline__ void cp4(unsigned dst, const void* src) {
    asm volatile("cp.async.ca.shared.global [%0], [%1], 4;" :: "r"(dst), "l"(src));
}
#define CP_COMMIT()  asm volatile("cp.async.commit_group;")
#define CP_WAIT(n)   asm volatile("cp.async.wait_group %0;" :: "n"(n))

// ---------------- position map ---------------------------------------------
__global__ __launch_bounds__(256) void k_map_init() {
    int t = blockIdx.x * 256 + threadIdx.x;
    if (t < CACHE) g_posmap[t] = -1;
}
__global__ __launch_bounds__(32) void k_map_scatter(const int* __restrict__ pos, int n) {
    int i = threadIdx.x;
    if (i < n) {
        int p = pos[i];
        if (p >= 0 && p < CACHE) g_posmap[p] = i;
    }
}

// ---------------- 32-row GEMM, double-buffered cp.async --------------------
__device__ __forceinline__ void gemm_32rows(const float* __restrict__ X,
                                            const float* __restrict__ W,
                                            const float* __restrict__ bias,
                                            float scale,
                                            float* __restrict__ Y,
                                            int c0) {
    __shared__ float ws[2][32 * 68];
    __shared__ float xs[2][32 * 68];
    int tid = threadIdx.x;
    int cL  = tid & 31;
    int rG  = tid >> 5;
    unsigned long long acc[4] = {0ull, 0ull, 0ull, 0ull};

    // prologue: stage 0
#pragma unroll
    for (int it = 0; it < 2; ++it) {
        int f = tid + it * 256;
        int row = f >> 4, k4 = f & 15;
        cp16(smem_u32(&ws[0][row * 68 + k4 * 4]),
             W + (size_t)(c0 + row) * N_STATE + k4 * 4);
        cp16(smem_u32(&xs[0][row * 68 + k4 * 4]),
             X + (size_t)row * N_STATE + k4 * 4);
    }
    CP_COMMIT();

    int s = 0;
    for (int kt = 0; kt < N_STATE; kt += 64, s ^= 1) {
        if (kt + 64 < N_STATE) {
#pragma unroll
            for (int it = 0; it < 2; ++it) {
                int f = tid + it * 256;
                int row = f >> 4, k4 = f & 15;
                cp16(smem_u32(&ws[s ^ 1][row * 68 + k4 * 4]),
                     W + (size_t)(c0 + row) * N_STATE + kt + 64 + k4 * 4);
                cp16(smem_u32(&xs[s ^ 1][row * 68 + k4 * 4]),
                     X + (size_t)row * N_STATE + kt + 64 + k4 * 4);
            }
        }
        CP_COMMIT();
        CP_WAIT(1);
        __syncthreads();
#pragma unroll
        for (int k4 = 0; k4 < 16; ++k4) {
            ulonglong2 wv = *(const ulonglong2*)(&ws[s][cL * 68 + k4 * 4]);
#pragma unroll
            for (int j = 0; j < 4; ++j) {
                ulonglong2 xv = *(const ulonglong2*)(&xs[s][(rG * 4 + j) * 68 + k4 * 4]);
                fmaf2(acc[j], wv.x, xv.x);
                fmaf2(acc[j], wv.y, xv.y);
            }
        }
        __syncthreads();
    }
    int c = c0 + cL;
    float b = bias ? bias[c] : 0.0f;
#pragma unroll
    for (int j = 0; j < 4; ++j) {
        float2 sv = unpack2(acc[j]);
        Y[(size_t)(rG * 4 + j) * N_STATE + c] = (sv.x + sv.y + b) * scale;
    }
}

__global__ __launch_bounds__(256) void k_qkv_gemm(const float* __restrict__ x,
                                                  const float* __restrict__ Wq,
                                                  const float* __restrict__ bq,
                                                  const float* __restrict__ Wk,
                                                  const float* __restrict__ Wv,
                                                  const float* __restrict__ bv) {
    int m = blockIdx.y;
    const float* W    = (m == 0) ? Wq : ((m == 1) ? Wk : Wv);
    const float* bias = (m == 0) ? bq : ((m == 1) ? (const float*)nullptr : bv);
    float scale       = (m == 0) ? 0.125f : 1.0f;
    float* Y          = (m == 0) ? g_q : ((m == 1) ? g_k : g_v);
    gemm_32rows(x, W, bias, scale, Y, blockIdx.x * 32);
}

__global__ __launch_bounds__(256) void k_out_gemm(const float* __restrict__ W,
                                                   const float* __restrict__ b,
                                                   float* __restrict__ Y) {
    gemm_32rows(g_oattn, W, b, 1.0f, Y, blockIdx.x * 32);
}

// ---------------- fused cache-copy + tf32-mma split-T attention ------------
// smem: qs[32*76] | S[128*37] | kK[128*76] | kV[128*76]
#define SM_QS  0
#define SM_S   (32 * KV_STR)                       // 2432
#define SM_KK  (SM_S + 128 * S_STR)                // 7168
#define SM_KV  (SM_KK + 128 * KV_STR)              // 16896
#define ATTN_SMEM_FLOATS (SM_KV + 128 * KV_STR)    // 26624
#define ATTN_SMEM_BYTES  (ATTN_SMEM_FLOATS * 4)    // 106496

__global__ __launch_bounds__(256, 2) void k_attn(const float* __restrict__ kin,
                                                 const float* __restrict__ vin,
                                                 const float* __restrict__ mask,
                                                 float* __restrict__ kc,
                                                 float* __restrict__ vc) {
    extern __shared__ float sm[];
    float* qs = sm + SM_QS;
    float* S  = sm + SM_S;
    float* kK = sm + SM_KK;
    float* kV = sm + SM_KV;

    int h   = blockIdx.x;
    int c   = blockIdx.y;
    int t0  = c * CHUNK;
    int tid = threadIdx.x;

    // ---- group 1: q tile + mask tile (staged into S slots) ----
#pragma unroll
    for (int it = 0; it < 2; ++it) {
        int i = tid + it * 256;               // 0..511 float4s of q
        int row = i >> 4, d4 = i & 15;
        cp16(smem_u32(qs + row * KV_STR + d4 * 4),
             g_q + (size_t)row * N_STATE + h * HEAD_DIM + d4 * 4);
    }
#pragma unroll
    for (int it = 0; it < 16; ++it) {
        int f = tid + it * 256;               // 0..4095
        int q = f >> 7, t = f & 127;
        cp4(smem_u32(S + t * S_STR + q), mask + (size_t)q * CACHE + t0 + t);
    }
    CP_COMMIT();

    // ---- group 2: K tile (posmap-substituted) ----
#pragma unroll
    for (int it = 0; it < 8; ++it) {
        int f = tid + it * 256;               // 0..2047
        int row = f >> 4, d4 = f & 15;
        int tt = t0 + row;
        int mi = g_posmap[tt];
        const float* src = (mi >= 0) ? (g_k + (size_t)mi * N_STATE + h * HEAD_DIM)
                                     : (kin + (size_t)tt * N_STATE + h * HEAD_DIM);
        cp16(smem_u32(kK + row * KV_STR + d4 * 4), src + d4 * 4);
    }
    CP_COMMIT();

    // ---- group 3: V tile ----
#pragma unroll
    for (int it = 0; it < 8; ++it) {
        int f = tid + it * 256;
        int row = f >> 4, d4 = f & 15;
        int tt = t0 + row;
        int mi = g_posmap[tt];
        const float* src = (mi >= 0) ? (g_v + (size_t)mi * N_STATE + h * HEAD_DIM)
                                     : (vin + (size_t)tt * N_STATE + h * HEAD_DIM);
        cp16(smem_u32(kV + row * KV_STR + d4 * 4), src + d4 * 4);
    }
    CP_COMMIT();

    CP_WAIT(1);            // q + mask + K ready (V in flight)
    __syncthreads();

    // kc copy from smem (overlaps with QK)
#pragma unroll
    for (int it = 0; it < 8; ++it) {
        int f = tid + it * 256;
        int row = f >> 4, d4 = f & 15;
        int tt = t0 + row;
        float4 vv = *(const float4*)(kK + row * KV_STR + d4 * 4);
        *(float4*)(kc + (size_t)tt * N_STATE + h * HEAD_DIM + d4 * 4) = vv;
    }

    int w    = tid >> 5;
    int lane = tid & 31;
    int g    = lane >> 2;
    int tg   = lane & 3;

    // ---- QK^T via tf32 mma: D[128 tok x 32 q]; warp w owns 16 tokens ----
    {
        int tokb = w * 16;
        float d[4][4];
#pragma unroll
        for (int j = 0; j < 4; ++j)
#pragma unroll
            for (int r = 0; r < 4; ++r) d[j][r] = 0.f;

#pragma unroll
        for (int k0 = 0; k0 < HEAD_DIM; k0 += 8) {
            unsigned a[4];
            a[0] = f2tf(kK[(tokb + g) * KV_STR + k0 + tg]);
            a[1] = f2tf(kK[(tokb + 8 + g) * KV_STR + k0 + tg]);
            a[2] = f2tf(kK[(tokb + g) * KV_STR + k0 + tg + 4]);
            a[3] = f2tf(kK[(tokb + 8 + g) * KV_STR + k0 + tg + 4]);
#pragma unroll
            for (int j = 0; j < 4; ++j) {
                unsigned b[2];
                b[0] = f2tf(qs[(j * 8 + g) * KV_STR + k0 + tg]);
                b[1] = f2tf(qs[(j * 8 + g) * KV_STR + k0 + tg + 4]);
                mma_tf32(d[j], a, b);
            }
        }
        // epilogue: add staged mask, store scores; pair q/q+1 for STS.64 merge
#pragma unroll
        for (int j = 0; j < 4; ++j) {
            int q  = j * 8 + 2 * tg;
            int r0 = tokb + g, r1 = tokb + 8 + g;
            float2 s0 = make_float2(S[r0 * S_STR + q] + d[j][0],
                                    S[r0 * S_STR + q + 1] + d[j][1]);
            S[r0 * S_STR + q]     = s0.x;
            S[r0 * S_STR + q + 1] = s0.y;
            float2 s1 = make_float2(S[r1 * S_STR + q] + d[j][2],
                                    S[r1 * S_STR + q + 1] + d[j][3]);
            S[r1 * S_STR + q]     = s1.x;
            S[r1 * S_STR + q + 1] = s1.y;
        }
    }
    __syncthreads();

    // ---- chunk-local softmax: warp w owns queries 4w..4w+3 ----
    {
#pragma unroll
        for (int qq = 0; qq < 4; ++qq) {
            int q = w * 4 + qq;
            float vals[4];
            float mx = -1e30f;
#pragma unroll
            for (int i = 0; i < 4; ++i) {
                vals[i] = S[(lane + 32 * i) * S_STR + q];
                mx = fmaxf(mx, vals[i]);
            }
#pragma unroll
            for (int off = 16; off > 0; off >>= 1)
                mx = fmaxf(mx, __shfl_xor_sync(0xffffffffu, mx, off));
            float sum = 0.f;
#pragma unroll
            for (int i = 0; i < 4; ++i) {
                float p = __expf(vals[i] - mx);
                S[(lane + 32 * i) * S_STR + q] = p;
                sum += p;
            }
#pragma unroll
            for (int off = 16; off > 0; off >>= 1)
                sum += __shfl_xor_sync(0xffffffffu, sum, off);
            if (lane == 0) {
                int pi = (h * NCHUNK + c) * N_CTX + q;
                g_m[pi] = mx;
                g_l[pi] = sum;
            }
        }
    }

    CP_WAIT(0);            // V ready
    __syncthreads();       // publishes softmax S writes

    // vc copy from smem
#pragma unroll
    for (int it = 0; it < 8; ++it) {
        int f = tid + it * 256;
        int row = f >> 4, d4 = f & 15;
        int tt = t0 + row;
        float4 vv = *(const float4*)(kV + row * KV_STR + d4 * 4);
        *(float4*)(vc + (size_t)tt * N_STATE + h * HEAD_DIM + d4 * 4) = vv;
    }

    // ---- PV via tf32 mma: O[32 q x 64 d] = S^T(32x128) @ V(128x64) ----
    {
        int q0 = (w & 1) * 16;       // m-tile
        int nb = (w >> 1) * 2;       // first of 2 n-tiles (8 d each)
        float o[2][4];
#pragma unroll
        for (int j = 0; j < 2; ++j)
#pragma unroll
            for (int r = 0; r < 4; ++r) o[j][r] = 0.f;

#pragma unroll
        for (int kk = 0; kk < CHUNK; kk += 8) {
            unsigned a[4];
            a[0] = f2tf(S[(kk + tg) * S_STR + q0 + g]);
            a[1] = f2tf(S[(kk + tg) * S_STR + q0 + 8 + g]);
            a[2] = f2tf(S[(kk + tg + 4) * S_STR + q0 + g]);
            a[3] = f2tf(S[(kk + tg + 4) * S_STR + q0 + 8 + g]);
#pragma unroll
            for (int j = 0; j < 2; ++j) {
                int d0 = (nb + j) * 8;
                unsigned b[2];
                b[0] = f2tf(kV[(kk + tg) * KV_STR + d0 + g]);
                b[1] = f2tf(kV[(kk + tg + 4) * KV_STR + d0 + g]);
                mma_tf32(o[j], a, b);
            }
        }
        int pi_base = (h * NCHUNK + c) * N_CTX;
#pragma unroll
        for (int j = 0; j < 2; ++j) {
            int d0 = (nb + j) * 8 + 2 * tg;
            float* p0 = g_opart + (size_t)(pi_base + q0 + g) * HEAD_DIM + d0;
            p0[0] = o[j][0];
            p0[1] = o[j][1];
            float* p1 = g_opart + (size_t)(pi_base + q0 + 8 + g) * HEAD_DIM + d0;
            p1[0] = o[j][2];
            p1[1] = o[j][3];
        }
    }
}

// ---------------- split-T reduction ----------------------------------------
__global__ __launch_bounds__(64) void k_reduce() {
    int h = blockIdx.x >> 5;
    int q = blockIdx.x & 31;
    int d = threadIdx.x;
    __shared__ float smx[NCHUNK], sl[NCHUNK];
#pragma unroll
    for (int i = 0; i < NCHUNK / 64; ++i) {
        int cc = d + i * 64;
        smx[cc] = g_m[(h * NCHUNK + cc) * N_CTX + q];
        sl[cc]  = g_l[(h * NCHUNK + cc) * N_CTX + q];
    }
    __syncthreads();
    float M = -1e30f;
#pragma unroll
    for (int cc = 0; cc < NCHUNK; ++cc) M = fmaxf(M, smx[cc]);
    float L = 0.f, o = 0.f;
#pragma unroll 8
    for (int cc = 0; cc < NCHUNK; ++cc) {
        float wc = __expf(smx[cc] - M);
        L += wc * sl[cc];
        o += wc * g_opart[((size_t)(h * NCHUNK + cc) * N_CTX + q) * HEAD_DIM + d];
    }
    g_oattn[(size_t)q * N_STATE + h * HEAD_DIM + d] = o / L;
}

// ---------------- launch ---------------------------------------------------
extern "C" void kernel_launch(void* const* d_in, const int* in_sizes, int n_in,
                              void* d_out, int out_size) {
    (void)n_in; (void)out_size;
    const float* x    = (const float*)d_in[0];
    const float* kin  = (const float*)d_in[1];
    const float* vin  = (const float*)d_in[2];
    const int*   pos  = (const int*)d_in[3];
    const float* mask = (const float*)d_in[4];
    const float* Wq   = (const float*)d_in[5];
    const float* bq   = (const float*)d_in[6];
    const float* Wk   = (const float*)d_in[7];
    const float* Wv   = (const float*)d_in[8];
    const float* bv   = (const float*)d_in[9];
    const float* Wout = (const float*)d_in[10];
    const float* bout = (const float*)d_in[11];

    float* out = (float*)d_out;
    float* kc  = out + (size_t)N_CTX * N_STATE;
    float* vc  = kc + (size_t)CACHE * N_STATE;

    (void)cudaFuncSetAttribute(k_attn, cudaFuncAttributeMaxDynamicSharedMemorySize,
                               ATTN_SMEM_BYTES);

    k_map_init<<<CACHE / 256, 256>>>();
    k_map_scatter<<<1, 32>>>(pos, in_sizes[3]);
    k_qkv_gemm<<<dim3(N_STATE / 32, 3), 256>>>(x, Wq, bq, Wk, Wv, bv);
    k_attn<<<dim3(N_HEAD, NCHUNK), 256, ATTN_SMEM_BYTES>>>(kin, vin, mask, kc, vc);
    k_reduce<<<N_HEAD * N_CTX, 64>>>();
    k_out_gemm<<<N_STATE / 32, 256>>>(Wout, bout, out);
}